// round 8
// baseline (speedup 1.0000x reference)
#include <cuda_runtime.h>
#include <cuda_fp16.h>
#include <cstdint>

#define N_NODES 100000
#define D 128
#define E_MAX 600000
#define TILE_M 64
#define NUM_TILES ((N_NODES + TILE_M - 1) / TILE_M)   // 1563
#define THREADS 256
#define GRID_GEMM 304   // 2 CTAs per SM
#define PITCH_H 272
#define SCAN_B 1024
#define NUM_SB ((N_NODES + SCAN_B - 1) / SCAN_B)      // 98

__device__ float g_agg[(size_t)N_NODES * D];
__device__ uint32_t g_cnt[N_NODES];
__device__ uint32_t g_cur[N_NODES];
__device__ uint32_t g_base[N_NODES];
__device__ uint32_t g_bsum[NUM_SB];
__device__ uint32_t g_boff[NUM_SB];
__device__ uint2    g_edge[E_MAX];

__device__ __forceinline__ uint32_t packh2(float lo, float hi) {
    __half2 h = __floats2half2_rn(lo, hi);
    return *reinterpret_cast<uint32_t*>(&h);
}

__device__ __forceinline__ void mma_f16(float* d, uint32_t a0, uint32_t a1,
                                        uint32_t a2, uint32_t a3,
                                        uint32_t b0, uint32_t b1) {
    asm volatile(
        "mma.sync.aligned.m16n8k16.row.col.f32.f16.f16.f32 "
        "{%0,%1,%2,%3}, {%4,%5,%6,%7}, {%8,%9}, {%0,%1,%2,%3};"
        : "+f"(d[0]), "+f"(d[1]), "+f"(d[2]), "+f"(d[3])
        : "r"(a0), "r"(a1), "r"(a2), "r"(a3), "r"(b0), "r"(b1));
}

__device__ __forceinline__ void perm_store16(uint32_t* dst, const float* v) {
    uint4 lo = make_uint4(packh2(v[0], v[1]),  packh2(v[8], v[9]),
                          packh2(v[2], v[3]),  packh2(v[10], v[11]));
    uint4 hi = make_uint4(packh2(v[4], v[5]),  packh2(v[12], v[13]),
                          packh2(v[6], v[7]),  packh2(v[14], v[15]));
    *(uint4*)dst = lo;
    *(uint4*)(dst + 4) = hi;
}

// ---------------- CSR build ----------------
__global__ void zero_cnt_kernel() {
    int i = blockIdx.x * blockDim.x + threadIdx.x;
    if (i < N_NODES) { g_cnt[i] = 0; g_cur[i] = 0; }
}

__global__ void hist_kernel(const int* __restrict__ ei, int E) {
    int e = blockIdx.x * blockDim.x + threadIdx.x;
    if (e >= E) return;
    atomicAdd(&g_cnt[ei[E + e]], 1u);
}

__global__ void __launch_bounds__(SCAN_B) scan1_kernel() {
    __shared__ uint32_t s[SCAN_B];
    int gi = blockIdx.x * SCAN_B + threadIdx.x;
    uint32_t v = (gi < N_NODES) ? g_cnt[gi] : 0u;
    s[threadIdx.x] = v;
    __syncthreads();
    uint32_t sum = v;
#pragma unroll
    for (int off = 1; off < SCAN_B; off <<= 1) {
        uint32_t t = (threadIdx.x >= off) ? s[threadIdx.x - off] : 0u;
        __syncthreads();
        sum += t;
        s[threadIdx.x] = sum;
        __syncthreads();
    }
    if (gi < N_NODES) g_base[gi] = sum - v;
    if (threadIdx.x == SCAN_B - 1) g_bsum[blockIdx.x] = sum;
}

__global__ void scan2_kernel() {
    __shared__ uint32_t s[128];
    int i = threadIdx.x;
    uint32_t v = (i < NUM_SB) ? g_bsum[i] : 0u;
    s[i] = v;
    __syncthreads();
    uint32_t sum = v;
#pragma unroll
    for (int off = 1; off < 128; off <<= 1) {
        uint32_t t = (i >= off) ? s[i - off] : 0u;
        __syncthreads();
        sum += t;
        s[i] = sum;
        __syncthreads();
    }
    if (i < NUM_SB) g_boff[i] = sum - v;
}

__global__ void fill_kernel(const int* __restrict__ ei,
                            const float* __restrict__ ew, int E) {
    int e = blockIdx.x * blockDim.x + threadIdx.x;
    if (e >= E) return;
    int col = ei[E + e];
    uint32_t slot = g_base[col] + g_boff[col >> 10] + atomicAdd(&g_cur[col], 1u);
    g_edge[slot] = make_uint2((uint32_t)ei[e], __float_as_uint(ew[e]));
}

// ---------------- gather: warp per node, 4-way unrolled ----------------
__global__ void __launch_bounds__(256) gather_kernel(const float* __restrict__ x) {
    int node = blockIdx.x * 8 + (threadIdx.x >> 5);
    if (node >= N_NODES) return;
    int lane = threadIdx.x & 31;
    uint32_t start = g_base[node] + g_boff[node >> 10];
    uint32_t cnt = g_cnt[node];
    const float4* xb = (const float4*)x;
    float4 a0 = make_float4(0.f, 0.f, 0.f, 0.f);
    float4 a1 = a0, a2 = a0, a3 = a0;
    uint32_t i = 0;
    for (; i + 4 <= cnt; i += 4) {
        uint2 e0 = g_edge[start + i];
        uint2 e1 = g_edge[start + i + 1];
        uint2 e2 = g_edge[start + i + 2];
        uint2 e3 = g_edge[start + i + 3];
        float4 v0 = xb[(size_t)e0.x * 32 + lane];
        float4 v1 = xb[(size_t)e1.x * 32 + lane];
        float4 v2 = xb[(size_t)e2.x * 32 + lane];
        float4 v3 = xb[(size_t)e3.x * 32 + lane];
        float w0 = __uint_as_float(e0.y), w1 = __uint_as_float(e1.y);
        float w2 = __uint_as_float(e2.y), w3 = __uint_as_float(e3.y);
        a0.x += w0 * v0.x; a0.y += w0 * v0.y; a0.z += w0 * v0.z; a0.w += w0 * v0.w;
        a1.x += w1 * v1.x; a1.y += w1 * v1.y; a1.z += w1 * v1.z; a1.w += w1 * v1.w;
        a2.x += w2 * v2.x; a2.y += w2 * v2.y; a2.z += w2 * v2.z; a2.w += w2 * v2.w;
        a3.x += w3 * v3.x; a3.y += w3 * v3.y; a3.z += w3 * v3.z; a3.w += w3 * v3.w;
    }
    for (; i < cnt; i++) {
        uint2 e0 = g_edge[start + i];
        float4 v0 = xb[(size_t)e0.x * 32 + lane];
        float w0 = __uint_as_float(e0.y);
        a0.x += w0 * v0.x; a0.y += w0 * v0.y; a0.z += w0 * v0.z; a0.w += w0 * v0.w;
    }
    a0.x += a1.x + a2.x + a3.x;
    a0.y += a1.y + a2.y + a3.y;
    a0.z += a1.z + a2.z + a3.z;
    a0.w += a1.w + a2.w + a3.w;
    ((float4*)g_agg)[(size_t)node * 32 + lane] = a0;
}

// ---------------- fp16 m16n8k16 dual-GEMM epilogue, 2 CTAs/SM ----------------
__global__ void __launch_bounds__(THREADS, 2)
gemm_kernel(const float* __restrict__ x,
            const float* __restrict__ W1, const float* __restrict__ b1,
            const float* __restrict__ W2, const float* __restrict__ b2,
            float* __restrict__ out) {
    extern __shared__ char smc[];
    uint16_t* Ws = (uint16_t*)smc;                       // [128][PITCH_H]
    uint16_t* As = Ws + 128 * PITCH_H;                   // [64][PITCH_H]
    float* bias  = (float*)(As + TILE_M * PITCH_H);      // [128]

    const int tid  = threadIdx.x;
    const int lane = tid & 31;
    const int wid  = tid >> 5;
    const int wrow = wid >> 2;
    const int wcol = wid & 3;
    const int g    = lane >> 2;
    const int tg   = lane & 3;

    for (int i = tid; i < 128 * 16; i += THREADS) {
        int c = i >> 4, o = i & 15;
        const float* src = (o < 8) ? (W1 + c * 128 + o * 16)
                                   : (W2 + c * 128 + (o - 8) * 16);
        float v[16];
        *(float4*)&v[0]  = *(const float4*)(src);
        *(float4*)&v[4]  = *(const float4*)(src + 4);
        *(float4*)&v[8]  = *(const float4*)(src + 8);
        *(float4*)&v[12] = *(const float4*)(src + 12);
        perm_store16((uint32_t*)&Ws[c * PITCH_H + o * 16], v);
    }
    for (int i = tid; i < 128; i += THREADS) bias[i] = b1[i] + b2[i];
    __syncthreads();

    float bias_c[4][2];
#pragma unroll
    for (int nf = 0; nf < 4; nf++) {
        int col = wcol * 32 + nf * 8 + tg * 2;
        bias_c[nf][0] = bias[col];
        bias_c[nf][1] = bias[col + 1];
    }

    const int rb = wrow * 32;
    const char* AsB = (const char*)As;
    const char* WsB = (const char*)Ws;

    for (int t = blockIdx.x; t < NUM_TILES; t += gridDim.x) {
        const int r0 = t * TILE_M;

#pragma unroll
        for (int it = 0; it < 4; it++) {
            int idx = it * THREADS + tid;
            int r = idx >> 4, o = idx & 15;
            int row = r0 + r;
            if (row >= N_NODES) row = N_NODES - 1;
            int q0 = (o & 7) * 4;
            float v[16];
#pragma unroll
            for (int j = 0; j < 4; j++) {
                float4 xv = ((const float4*)(x + (size_t)row * D))[q0 + j];
                float4 gv = ((const float4*)(g_agg + (size_t)row * D))[q0 + j];
                if (o < 8) {
                    v[j*4+0] = gv.x + xv.x; v[j*4+1] = gv.y + xv.y;
                    v[j*4+2] = gv.z + xv.z; v[j*4+3] = gv.w + xv.w;
                } else {
                    v[j*4+0] = gv.x * xv.x; v[j*4+1] = gv.y * xv.y;
                    v[j*4+2] = gv.z * xv.z; v[j*4+3] = gv.w * xv.w;
                }
            }
            perm_store16((uint32_t*)&As[r * PITCH_H + o * 16], v);
        }
        __syncthreads();

        float acc[2][4][4];
#pragma unroll
        for (int mf = 0; mf < 2; mf++)
#pragma unroll
            for (int nf = 0; nf < 4; nf++)
#pragma unroll
                for (int j = 0; j < 4; j++) acc[mf][nf][j] = 0.f;

#pragma unroll 4
        for (int ks = 0; ks < 16; ks++) {
            const int goff = ks * 32 + tg * 8;
            uint2 aLo[2], aHi[2];
#pragma unroll
            for (int mf = 0; mf < 2; mf++) {
                int rbyte = (rb + mf * 16 + g) * PITCH_H * 2;
                aLo[mf] = *(const uint2*)(AsB + rbyte + goff);
                aHi[mf] = *(const uint2*)(AsB + rbyte + 8 * PITCH_H * 2 + goff);
            }
#pragma unroll
            for (int nf = 0; nf < 4; nf++) {
                int cbyte = (wcol * 32 + nf * 8 + g) * PITCH_H * 2;
                uint2 bf = *(const uint2*)(WsB + cbyte + goff);
                mma_f16(acc[0][nf], aLo[0].x, aHi[0].x, aLo[0].y, aHi[0].y, bf.x, bf.y);
                mma_f16(acc[1][nf], aLo[1].x, aHi[1].x, aLo[1].y, aHi[1].y, bf.x, bf.y);
            }
        }

#pragma unroll
        for (int mf = 0; mf < 2; mf++) {
            int row0 = r0 + rb + mf * 16 + g;
            int row1 = row0 + 8;
#pragma unroll
            for (int nf = 0; nf < 4; nf++) {
                int col = wcol * 32 + nf * 8 + tg * 2;
                float h0 = acc[mf][nf][0] + bias_c[nf][0];
                float h1 = acc[mf][nf][1] + bias_c[nf][1];
                float h2 = acc[mf][nf][2] + bias_c[nf][0];
                float h3 = acc[mf][nf][3] + bias_c[nf][1];
                float2 v0 = make_float2(h0 > 0.f ? h0 : 0.2f * h0,
                                        h1 > 0.f ? h1 : 0.2f * h1);
                float2 v1 = make_float2(h2 > 0.f ? h2 : 0.2f * h2,
                                        h3 > 0.f ? h3 : 0.2f * h3);
                if (row0 < N_NODES) *(float2*)(out + (size_t)row0 * D + col) = v0;
                if (row1 < N_NODES) *(float2*)(out + (size_t)row1 * D + col) = v1;
            }
        }
        __syncthreads();
    }
}

extern "C" void kernel_launch(void* const* d_in, const int* in_sizes, int n_in,
                              void* d_out, int out_size) {
    const float* x  = (const float*)d_in[0];
    const int*   ei = (const int*)d_in[1];
    const float* ew = (const float*)d_in[2];
    const float* W1 = (const float*)d_in[3];
    const float* b1 = (const float*)d_in[4];
    const float* W2 = (const float*)d_in[5];
    const float* b2 = (const float*)d_in[6];
    float* out = (float*)d_out;

    int E = in_sizes[2];

    zero_cnt_kernel<<<(N_NODES + 255) / 256, 256>>>();
    hist_kernel<<<(E + 255) / 256, 256>>>(ei, E);
    scan1_kernel<<<NUM_SB, SCAN_B>>>();
    scan2_kernel<<<1, 128>>>();
    fill_kernel<<<(E + 255) / 256, 256>>>(ei, ew, E);
    gather_kernel<<<(N_NODES + 7) / 8, 256>>>(x);

    const int smem_bytes = (128 + TILE_M) * PITCH_H * 2 + 128 * 4;
    cudaFuncSetAttribute(gemm_kernel,
                         cudaFuncAttributeMaxDynamicSharedMemorySize, smem_bytes);
    gemm_kernel<<<GRID_GEMM, THREADS, smem_bytes>>>(x, W1, b1, W2, b2, out);
}